// round 11
// baseline (speedup 1.0000x reference)
#include <cuda_runtime.h>
#include <cuda_fp16.h>
#include <stdint.h>

#define MAX_NODES 100000
#define NIN 5
#define NOUT 16
#define CAP 96   // max in-degree bucket capacity (lambda=32 Poisson; huge margin)

// Scratch (allocation-free rule: __device__ globals).
__device__ __align__(16) uint4 g_msg16[MAX_NODES];        // 8 halves: {dis*a0..a4, dis, 0, 0}
__device__ __align__(16) uint4 g_bucket[MAX_NODES * CAP]; // 16B messages, 153.6 MB
__device__ float g_dis[MAX_NODES];
__device__ int   g_cnt[MAX_NODES];   // in-degree (real edges), from k_deg
__device__ int   g_pos[MAX_NODES];   // placement cursor for k_place
__device__ int   g_is32 = 0;  // dtype flag: set-only, dtype constant across replays

// ---------------- kernels ----------------

// Fused: cnt=0, pos=0, dtype detect.
// If int64, odd 32-bit words of edge_index are high halves of values in
// [0,1e5) -> all zero. If int32 they are node ids, mostly nonzero.
__global__ void k_init(int n, const unsigned int* __restrict__ buf) {
    int i = blockIdx.x * blockDim.x + threadIdx.x;
    if (i < n) { g_cnt[i] = 0; g_pos[i] = 0; }
    if (i < 65536 && buf[2 * i + 1] != 0) g_is32 = 1;   // 512KB probe, safe
}

__device__ __forceinline__ int clampi(int v, int n) {
    return min(max(v, 0), n - 1);
}

// degree over target (col): 2 edges per thread, vector loads
__global__ void k_deg(const void* __restrict__ ei, int E, int n) {
    int t = blockIdx.x * blockDim.x + threadIdx.x;
    int e = t * 2;
    if (e >= E) return;
    int c0, c1;
    bool two = (e + 1 < E);
    if (g_is32) {
        const int* p = (const int*)ei + E;
        if (two) { int2 v = *(const int2*)(p + e); c0 = v.x; c1 = v.y; }
        else { c0 = p[e]; c1 = 0; }
    } else {
        const long long* p = (const long long*)ei + E;
        if (two) { longlong2 v = *(const longlong2*)(p + e); c0 = (int)v.x; c1 = (int)v.y; }
        else { c0 = (int)p[e]; c1 = 0; }
    }
    atomicAdd(&g_cnt[clampi(c0, n)], 1);
    if (two) atomicAdd(&g_cnt[clampi(c1, n)], 1);
}

// per node: dis = (cnt+1)^-1/2; msg16 = fp16{dis*atom[0..4], dis, 0, 0}
__global__ void k_pre(const float* __restrict__ atom, int n) {
    int i = blockIdx.x * blockDim.x + threadIdx.x;
    if (i >= n) return;
    float dis = rsqrtf((float)(g_cnt[i] + 1));  // +1 self loop
    g_dis[i] = dis;
    float a0 = atom[i * NIN + 0], a1 = atom[i * NIN + 1], a2 = atom[i * NIN + 2];
    float a3 = atom[i * NIN + 3], a4 = atom[i * NIN + 4];
    __half2 h0 = __floats2half2_rn(dis * a0, dis * a1);
    __half2 h1 = __floats2half2_rn(dis * a2, dis * a3);
    __half2 h2 = __floats2half2_rn(dis * a4, dis);
    uint4 m;
    m.x = *reinterpret_cast<unsigned int*>(&h0);
    m.y = *reinterpret_cast<unsigned int*>(&h1);
    m.z = *reinterpret_cast<unsigned int*>(&h2);
    m.w = 0;
    g_msg16[i] = m;
}

// Place message copies into target buckets: 2 edges per thread.
// Gather (16B, independent) + counter atomic + scattered 16B store.
__global__ void k_place(const void* __restrict__ ei, int E, int n) {
    int t = blockIdx.x * blockDim.x + threadIdx.x;
    int e = t * 2;
    if (e >= E) return;
    int r0, c0, r1, c1;
    bool two = (e + 1 < E);
    if (g_is32) {
        const int* p = (const int*)ei;
        if (two) {
            int2 rv = *(const int2*)(p + e);
            int2 cv = *(const int2*)(p + E + e);
            r0 = rv.x; r1 = rv.y; c0 = cv.x; c1 = cv.y;
        } else { r0 = p[e]; c0 = p[E + e]; r1 = c1 = 0; }
    } else {
        const long long* p = (const long long*)ei;
        if (two) {
            longlong2 rv = *(const longlong2*)(p + e);
            longlong2 cv = *(const longlong2*)(p + E + e);
            r0 = (int)rv.x; r1 = (int)rv.y; c0 = (int)cv.x; c1 = (int)cv.y;
        } else { r0 = (int)p[e]; c0 = (int)p[E + e]; r1 = c1 = 0; }
    }
    uint4 m0 = g_msg16[clampi(r0, n)];
    c0 = clampi(c0, n);
    int p0 = atomicAdd(&g_pos[c0], 1);
    g_bucket[c0 * CAP + min(p0, CAP - 1)] = m0;
    if (two) {
        uint4 m1 = g_msg16[clampi(r1, n)];
        c1 = clampi(c1, n);
        int p1 = atomicAdd(&g_pos[c1], 1);
        g_bucket[c1 * CAP + min(p1, CAP - 1)] = m1;
    }
}

__device__ __forceinline__ void acc_msg(float* s, uint4 m) {
    float2 f0 = __half22float2(*reinterpret_cast<__half2*>(&m.x));
    float2 f1 = __half22float2(*reinterpret_cast<__half2*>(&m.y));
    float2 f2 = __half22float2(*reinterpret_cast<__half2*>(&m.z));
    s[0] += f0.x; s[1] += f0.y; s[2] += f1.x;
    s[3] += f1.y; s[4] += f2.x; s[5] += f2.y;
}

// Streaming aggregate + fused matvec epilogue. 4 threads per node.
// out[c] = relu(dis_c * (W @ s[0..4] + s[5]*b)), sums over bucket + self.
__global__ void k_aggr(const float* __restrict__ atom,
                       const float* __restrict__ W,
                       const float* __restrict__ b,
                       float4* __restrict__ out4, int n) {
    int t = blockIdx.x * blockDim.x + threadIdx.x;
    int node = t >> 2;
    if (node >= n) return;
    int q = t & 3;

    const uint4* bp = &g_bucket[node * CAP];
    int cnt = min(g_cnt[node], CAP);

    float s[6] = {0.f, 0.f, 0.f, 0.f, 0.f, 0.f};
    float s2[6] = {0.f, 0.f, 0.f, 0.f, 0.f, 0.f};
    int k = q;
    for (; k + 4 < cnt; k += 8) {      // 2 independent 16B loads per iter
        uint4 ma = bp[k];
        uint4 mb = bp[k + 4];
        acc_msg(s, ma);
        acc_msg(s2, mb);
    }
    if (k < cnt) acc_msg(s, bp[k]);
#pragma unroll
    for (int i = 0; i < 6; i++) s[i] += s2[i];

    // reduce over the 4 lanes of this node (lane groups aligned to 4)
#pragma unroll
    for (int off = 1; off < 4; off <<= 1) {
#pragma unroll
        for (int i = 0; i < 6; i++)
            s[i] += __shfl_xor_sync(0xffffffff, s[i], off);
    }

    // self-loop term in fp32
    float dis = g_dis[node];
#pragma unroll
    for (int kk = 0; kk < NIN; kk++)
        s[kk] += dis * __ldg(&atom[node * NIN + kk]);
    float sb = s[5] + dis;

    // each lane computes its 4 output channels
    int j0 = q << 2;
    float r[4];
#pragma unroll
    for (int jj = 0; jj < 4; jj++) {
        int j = j0 + jj;
        float y = sb * __ldg(&b[j]);
#pragma unroll
        for (int kk = 0; kk < NIN; kk++)
            y = fmaf(s[kk], __ldg(&W[j * NIN + kk]), y);
        r[jj] = fmaxf(y * dis, 0.0f);
    }
    out4[node * 4 + q] = make_float4(r[0], r[1], r[2], r[3]);
}

// ---------------- launch ----------------

extern "C" void kernel_launch(void* const* d_in, const int* in_sizes, int n_in,
                              void* d_out, int out_size) {
    // Identify inputs by element count (all distinct):
    //   atom: 500000 fp32 | edge_index: 6400000 (int32 OR int64)
    //   W: 80 fp32        | b: 16 fp32
    const float* atom = nullptr;
    const void* ei = nullptr;
    const float* W = nullptr;
    const float* b = nullptr;
    int n = MAX_NODES, E = 0;

    for (int i = 0; i < n_in; i++) {
        int sz = in_sizes[i];
        if (sz == 16) b = (const float*)d_in[i];
        else if (sz == 80) W = (const float*)d_in[i];
        else if (sz > 1000000) { ei = d_in[i]; E = sz / 2; }
        else { atom = (const float*)d_in[i]; n = sz / NIN; }
    }
    if (n > MAX_NODES) n = MAX_NODES;

    float* out = (float*)d_out;
    const int B = 256;
    int initN = (n > 65536) ? n : 65536;
    k_init<<<(initN + B - 1) / B, B>>>(n, (const unsigned int*)ei);
    {
        int threads = (E + 1) / 2;
        k_deg<<<(threads + B - 1) / B, B>>>(ei, E, n);
    }
    k_pre<<<(n + B - 1) / B, B>>>(atom, n);
    {
        int threads = (E + 1) / 2;
        k_place<<<(threads + B - 1) / B, B>>>(ei, E, n);
    }
    k_aggr<<<(n * 4 + B - 1) / B, B>>>(atom, W, b, (float4*)out, n);
}

// round 12
// speedup vs baseline: 1.2232x; 1.2232x over previous
#include <cuda_runtime.h>
#include <stdint.h>

#define MAX_NODES 100000
#define NIN 5
#define NOUT 16

// Scratch (allocation-free rule: __device__ globals).
// NOTE: device globals are zero-initialized at module load; k_post re-zeroes
// g_acc/g_cnt after use so every replay starts clean (no init kernel needed).
__device__ __align__(16) float g_msg[MAX_NODES * 8];  // {dis*atom[0..4], dis, pad, pad}
__device__ __align__(16) float g_acc[MAX_NODES * 8];  // accumulators (6 of 8 used)
__device__ float g_dis[MAX_NODES];
__device__ int   g_cnt[MAX_NODES];   // in-degree of real edges
__device__ int   g_is32 = 0;  // dtype flag: set-only, dtype constant across replays

// ---------------- kernels ----------------

// Dtype detect: if int64, odd 32-bit words of edge_index are high halves of
// values in [0,1e5) -> all zero. If int32 they are node ids, mostly nonzero.
__global__ void k_detect(const unsigned int* __restrict__ buf) {
    int i = blockIdx.x * blockDim.x + threadIdx.x;   // 65536 threads, 512KB probe
    if (buf[2 * i + 1] != 0) g_is32 = 1;             // benign race, set-only
}

__device__ __forceinline__ int clampi(int v, int n) {
    return min(max(v, 0), n - 1);
}

// degree over target (col): 2 edges per thread, vector loads
__global__ void k_deg(const void* __restrict__ ei, int E, int n) {
    int t = blockIdx.x * blockDim.x + threadIdx.x;
    int e = t * 2;
    if (e >= E) return;
    int c0, c1;
    bool two = (e + 1 < E);
    if (g_is32) {
        const int* p = (const int*)ei + E;
        if (two) { int2 v = *(const int2*)(p + e); c0 = v.x; c1 = v.y; }
        else { c0 = p[e]; c1 = 0; }
    } else {
        const long long* p = (const long long*)ei + E;
        if (two) { longlong2 v = *(const longlong2*)(p + e); c0 = (int)v.x; c1 = (int)v.y; }
        else { c0 = (int)p[e]; c1 = 0; }
    }
    atomicAdd(&g_cnt[clampi(c0, n)], 1);
    if (two) atomicAdd(&g_cnt[clampi(c1, n)], 1);
}

// per node: dis = (cnt+1)^-1/2; msg = {dis*atom[0..4], dis, 0, 0}
__global__ void k_pre(const float* __restrict__ atom, int n) {
    int i = blockIdx.x * blockDim.x + threadIdx.x;
    if (i >= n) return;
    float dis = rsqrtf((float)(g_cnt[i] + 1));  // +1 self loop
    g_dis[i] = dis;
    float a0 = atom[i * NIN + 0], a1 = atom[i * NIN + 1], a2 = atom[i * NIN + 2];
    float a3 = atom[i * NIN + 3], a4 = atom[i * NIN + 4];
    float4* m4 = reinterpret_cast<float4*>(g_msg);
    m4[i * 2] = make_float4(dis * a0, dis * a1, dis * a2, dis * a3);
    m4[i * 2 + 1] = make_float4(dis * a4, dis, 0.f, 0.f);
}

__device__ __forceinline__ void red_add_v4(float* p, float4 v) {
    asm volatile("red.global.add.v4.f32 [%0], {%1, %2, %3, %4};"
                 :: "l"(p), "f"(v.x), "f"(v.y), "f"(v.z), "f"(v.w)
                 : "memory");
}
__device__ __forceinline__ void red_add_v2(float* p, float2 v) {
    asm volatile("red.global.add.v2.f32 [%0], {%1, %2};"
                 :: "l"(p), "f"(v.x), "f"(v.y)
                 : "memory");
}

__device__ __forceinline__ void scatter_one(int row, int col, int n) {
    row = clampi(row, n);
    col = clampi(col, n);
    float4 m0 = *reinterpret_cast<const float4*>(&g_msg[row * 8]);
    float2 m1 = *reinterpret_cast<const float2*>(&g_msg[row * 8 + 4]);
    red_add_v4(&g_acc[col * 8], m0);
    red_add_v2(&g_acc[col * 8 + 4], m1);
}

// 2 edges per thread: vector idx loads, 24B gather + v4/v2 RED per edge
__global__ void k_scatter(const void* __restrict__ ei, int E, int n) {
    int t = blockIdx.x * blockDim.x + threadIdx.x;
    int e = t * 2;
    if (e >= E) return;
    bool two = (e + 1 < E);
    int r0, c0, r1 = 0, c1 = 0;
    if (g_is32) {
        const int* p = (const int*)ei;
        if (two) {
            int2 rv = *(const int2*)(p + e);
            int2 cv = *(const int2*)(p + E + e);
            r0 = rv.x; r1 = rv.y; c0 = cv.x; c1 = cv.y;
        } else { r0 = p[e]; c0 = p[E + e]; }
    } else {
        const long long* p = (const long long*)ei;
        if (two) {
            longlong2 rv = *(const longlong2*)(p + e);
            longlong2 cv = *(const longlong2*)(p + E + e);
            r0 = (int)rv.x; r1 = (int)rv.y; c0 = (int)cv.x; c1 = (int)cv.y;
        } else { r0 = (int)p[e]; c0 = (int)p[E + e]; }
    }
    scatter_one(r0, c0, n);
    if (two) scatter_one(r1, c1, n);
}

// per node (4 threads): y = W*(s5 + dis*atom) + (s1+dis)*b ; out = relu(dis*y)
// Also self-cleans g_acc and g_cnt for the next graph replay.
__global__ void k_post(const float* __restrict__ atom,
                       const float* __restrict__ W,
                       const float* __restrict__ b,
                       float4* __restrict__ out4, int n) {
    int t = blockIdx.x * blockDim.x + threadIdx.x;
    int node = t >> 2;
    if (node >= n) return;
    int q = t & 3;
    int j0 = q << 2;

    float dis = g_dis[node];
    float v[NIN];
#pragma unroll
    for (int k = 0; k < NIN; k++)
        v[k] = g_acc[node * 8 + k] + dis * __ldg(&atom[node * NIN + k]);
    float sb = g_acc[node * 8 + 5] + dis;

    float r[4];
#pragma unroll
    for (int jj = 0; jj < 4; jj++) {
        int j = j0 + jj;
        float y = sb * __ldg(&b[j]);
#pragma unroll
        for (int k = 0; k < NIN; k++) y = fmaf(v[k], __ldg(&W[j * NIN + k]), y);
        r[jj] = fmaxf(y * dis, 0.0f);
    }
    out4[node * 4 + q] = make_float4(r[0], r[1], r[2], r[3]);

    // cleanup for next replay: lanes 0,1 zero the 2 float4s of acc; lane 2 cnt
    if (q < 2)
        reinterpret_cast<float4*>(g_acc)[node * 2 + q] = make_float4(0.f, 0.f, 0.f, 0.f);
    else if (q == 2)
        g_cnt[node] = 0;
}

// ---------------- launch ----------------

extern "C" void kernel_launch(void* const* d_in, const int* in_sizes, int n_in,
                              void* d_out, int out_size) {
    // Identify inputs by element count (all distinct):
    //   atom: 500000 fp32 | edge_index: 6400000 (int32 OR int64)
    //   W: 80 fp32        | b: 16 fp32
    const float* atom = nullptr;
    const void* ei = nullptr;
    const float* W = nullptr;
    const float* b = nullptr;
    int n = MAX_NODES, E = 0;

    for (int i = 0; i < n_in; i++) {
        int sz = in_sizes[i];
        if (sz == 16) b = (const float*)d_in[i];
        else if (sz == 80) W = (const float*)d_in[i];
        else if (sz > 1000000) { ei = d_in[i]; E = sz / 2; }
        else { atom = (const float*)d_in[i]; n = sz / NIN; }
    }
    if (n > MAX_NODES) n = MAX_NODES;

    float* out = (float*)d_out;
    const int B = 256;
    k_detect<<<65536 / B, B>>>((const unsigned int*)ei);
    {
        int threads = (E + 1) / 2;
        k_deg<<<(threads + B - 1) / B, B>>>(ei, E, n);
    }
    k_pre<<<(n + B - 1) / B, B>>>(atom, n);
    {
        int threads = (E + 1) / 2;
        k_scatter<<<(threads + B - 1) / B, B>>>(ei, E, n);
    }
    k_post<<<(n * 4 + B - 1) / B, B>>>(atom, W, b, (float4*)out, n);
}